// round 3
// baseline (speedup 1.0000x reference)
#include <cuda_runtime.h>

#define B_  2
#define S_  2048
#define D_  512
#define H_  8
#define DK_ 64
#define FF_ 2048
#define M_  (B_*S_)          // 4096 rows

// ---------------- scratch (no allocations allowed) ----------------
__device__ float g_q  [B_*H_*S_*DK_];
__device__ float g_k  [B_*H_*S_*DK_];
__device__ float g_v  [B_*H_*S_*DK_];
__device__ float g_ctx[M_*D_];
__device__ float g_pr [M_*D_];
__device__ float g_y  [M_*D_];
__device__ float g_ya [M_*D_];
__device__ float g_ya2[M_*D_];
__device__ float g_h  [M_*FF_];

// ---------------- GEMM: C[M,N] = A[M,K] @ W[N,K]^T + bias ----------------
// flags: bit0 = relu, bit1 = head-split store (N must be 512)
#define BM 128
#define BN 128
#define BK 16

__global__ __launch_bounds__(256) void gemm_kernel(
    const float* __restrict__ A, const float* __restrict__ W,
    const float* __restrict__ bias, float* __restrict__ C,
    int M, int N, int K, int flags)
{
    __shared__ float As[BK][BM + 4];
    __shared__ float Bs[BK][BN + 4];

    const int tid = threadIdx.x;
    const int tx  = tid & 15;
    const int ty  = tid >> 4;
    const int m0  = blockIdx.y * BM;
    const int n0  = blockIdx.x * BN;

    float acc[8][8];
    #pragma unroll
    for (int i = 0; i < 8; ++i)
        #pragma unroll
        for (int j = 0; j < 8; ++j) acc[i][j] = 0.f;

    for (int k0 = 0; k0 < K; k0 += BK) {
        #pragma unroll
        for (int t = 0; t < 2; ++t) {
            int f = tid + t * 256;
            int r = f >> 2;
            int c = (f & 3) << 2;
            float4 av = *reinterpret_cast<const float4*>(&A[(size_t)(m0 + r) * K + k0 + c]);
            As[c + 0][r] = av.x; As[c + 1][r] = av.y;
            As[c + 2][r] = av.z; As[c + 3][r] = av.w;
            float4 wv = *reinterpret_cast<const float4*>(&W[(size_t)(n0 + r) * K + k0 + c]);
            Bs[c + 0][r] = wv.x; Bs[c + 1][r] = wv.y;
            Bs[c + 2][r] = wv.z; Bs[c + 3][r] = wv.w;
        }
        __syncthreads();

        #pragma unroll
        for (int kk = 0; kk < BK; ++kk) {
            float a[8], b[8];
            #pragma unroll
            for (int i = 0; i < 8; ++i) a[i] = As[kk][ty * 8 + i];
            #pragma unroll
            for (int j = 0; j < 8; ++j) b[j] = Bs[kk][tx * 8 + j];
            #pragma unroll
            for (int i = 0; i < 8; ++i)
                #pragma unroll
                for (int j = 0; j < 8; ++j)
                    acc[i][j] = fmaf(a[i], b[j], acc[i][j]);
        }
        __syncthreads();
    }

    const bool relu   = flags & 1;
    const bool hsplit = flags & 2;
    #pragma unroll
    for (int i = 0; i < 8; ++i) {
        int m = m0 + ty * 8 + i;
        #pragma unroll
        for (int j = 0; j < 8; ++j) {
            int n = n0 + tx * 8 + j;
            float val = acc[i][j] + bias[n];
            if (relu) val = fmaxf(val, 0.f);
            if (hsplit) {
                int b  = m >> 11;
                int s  = m & (S_ - 1);
                int h  = n >> 6;
                int dk = n & (DK_ - 1);
                C[(((size_t)b * H_ + h) * S_ + s) * DK_ + dk] = val;
            } else {
                C[(size_t)m * N + n] = val;
            }
        }
    }
}

// ---------------- flash attention ----------------
// Q,K,V: [bh][s][dk] head-split. O: merged [b][s][h*DK+dk].
// 256 threads: 32 query rows per block, 8 threads per row (8 dims each).
// IMPORTANT: inner loop trip count is warp-uniform (full tile); causal
// masking is done via s = -1e30 so __shfl_xor_sync never diverges.
#define TK 64

__global__ __launch_bounds__(256) void attn_kernel(
    const float* __restrict__ Q, const float* __restrict__ Kh,
    const float* __restrict__ V, float* __restrict__ O, int causal)
{
    __shared__ float Ks[TK][DK_];
    __shared__ float Vs[TK][DK_];

    const int bh   = blockIdx.y;
    const int r0   = blockIdx.x * 32;
    const int tid  = threadIdx.x;
    const int row  = tid >> 3;
    const int lane = tid & 7;
    const int qrow = r0 + row;

    float q[8];
    {
        const float* qp = Q + ((size_t)bh * S_ + qrow) * DK_ + lane * 8;
        #pragma unroll
        for (int d = 0; d < 8; ++d) q[d] = qp[d];
    }
    float acc[8];
    #pragma unroll
    for (int d = 0; d < 8; ++d) acc[d] = 0.f;
    float mmax = -1e30f, lsum = 0.f;

    const int kend = causal ? (r0 + 32) : S_;   // # valid keys needed (rounded up by tile)
    for (int kt = 0; kt < kend; kt += TK) {
        const float* kb = Kh + ((size_t)bh * S_ + kt) * DK_;
        const float* vb = V  + ((size_t)bh * S_ + kt) * DK_;
        #pragma unroll
        for (int t = 0; t < 4; ++t) {
            int f  = tid + t * 256;
            int rr = f >> 4;
            int cc = (f & 15) << 2;
            *reinterpret_cast<float4*>(&Ks[rr][cc]) =
                *reinterpret_cast<const float4*>(&kb[rr * DK_ + cc]);
            *reinterpret_cast<float4*>(&Vs[rr][cc]) =
                *reinterpret_cast<const float4*>(&vb[rr * DK_ + cc]);
        }
        __syncthreads();

        // full-tile masking only needed on tiles overlapping the diagonal
        const bool need_mask = causal && (kt + TK > qrow + 1 - 3);  // conservative, warp-safe

        #pragma unroll 2
        for (int j = 0; j < TK; ++j) {
            float s = 0.f;
            const float* kr = &Ks[j][lane * 8];
            #pragma unroll
            for (int d = 0; d < 8; ++d) s = fmaf(q[d], kr[d], s);
            s += __shfl_xor_sync(0xffffffffu, s, 1);
            s += __shfl_xor_sync(0xffffffffu, s, 2);
            s += __shfl_xor_sync(0xffffffffu, s, 4);
            s *= 0.125f;                          // 1/sqrt(64)
            if (need_mask && (kt + j > qrow)) s = -1e30f;  // causal mask (p -> 0)

            float nm   = fmaxf(mmax, s);
            float corr = __expf(mmax - nm);
            float p    = __expf(s - nm);
            lsum = lsum * corr + p;
            mmax = nm;
            const float* vr = &Vs[j][lane * 8];
            #pragma unroll
            for (int d = 0; d < 8; ++d) acc[d] = acc[d] * corr + p * vr[d];
        }
        __syncthreads();
    }

    const float inv = 1.f / lsum;
    const int b = bh >> 3, h = bh & 7;
    float* op = O + ((size_t)(b * S_ + qrow)) * D_ + h * DK_ + lane * 8;
    #pragma unroll
    for (int d = 0; d < 8; ++d) op[d] = acc[d] * inv;
}

// ---------------- fused residual-add + LayerNorm ----------------
__global__ __launch_bounds__(256) void add_ln_kernel(
    const float* __restrict__ X, const float* __restrict__ Y,
    const float* __restrict__ gam, const float* __restrict__ bet,
    float* __restrict__ O)
{
    __shared__ float sh_s[8], sh_q[8];
    const int row = blockIdx.x;
    const int tid = threadIdx.x;
    const float* xp = X + (size_t)row * D_;
    const float* yp = Y + (size_t)row * D_;

    float v0 = xp[tid] + yp[tid];
    float v1 = xp[tid + 256] + yp[tid + 256];
    float s  = v0 + v1;
    float qq = v0 * v0 + v1 * v1;
    #pragma unroll
    for (int o = 16; o; o >>= 1) {
        s  += __shfl_xor_sync(0xffffffffu, s, o);
        qq += __shfl_xor_sync(0xffffffffu, qq, o);
    }
    if ((tid & 31) == 0) { sh_s[tid >> 5] = s; sh_q[tid >> 5] = qq; }
    __syncthreads();
    if (tid < 32) {
        float s2 = (tid < 8) ? sh_s[tid] : 0.f;
        float q2 = (tid < 8) ? sh_q[tid] : 0.f;
        #pragma unroll
        for (int o = 4; o; o >>= 1) {
            s2 += __shfl_xor_sync(0xffffffffu, s2, o);
            q2 += __shfl_xor_sync(0xffffffffu, q2, o);
        }
        if (tid == 0) { sh_s[0] = s2; sh_q[0] = q2; }
    }
    __syncthreads();

    const float mu  = sh_s[0] * (1.f / 512.f);
    const float var = sh_q[0] * (1.f / 512.f) - mu * mu;
    const float inv = rsqrtf(var + 1e-5f);
    O[(size_t)row * D_ + tid]       = (v0 - mu) * inv * gam[tid]       + bet[tid];
    O[(size_t)row * D_ + tid + 256] = (v1 - mu) * inv * gam[tid + 256] + bet[tid + 256];
}

// ---------------- orchestration ----------------
extern "C" void kernel_launch(void* const* d_in, const int* in_sizes, int n_in,
                              void* d_out, int out_size)
{
    const float* x_q   = (const float*)d_in[0];
    const float* x1    = (const float*)d_in[1];
    const float* x2    = (const float*)d_in[2];
    const float* sa_wq = (const float*)d_in[3];
    const float* sa_bq = (const float*)d_in[4];
    const float* sa_wk = (const float*)d_in[5];
    const float* sa_bk = (const float*)d_in[6];
    const float* sa_wv = (const float*)d_in[7];
    const float* sa_bv = (const float*)d_in[8];
    const float* ln1_g = (const float*)d_in[9];
    const float* ln1_b = (const float*)d_in[10];
    const float* in_w  = (const float*)d_in[11];
    const float* in_b  = (const float*)d_in[12];
    const float* out_w = (const float*)d_in[13];
    const float* out_b = (const float*)d_in[14];
    const float* ln2_g = (const float*)d_in[15];
    const float* ln2_b = (const float*)d_in[16];
    const float* w1    = (const float*)d_in[17];
    const float* b1    = (const float*)d_in[18];
    const float* w2    = (const float*)d_in[19];
    const float* b2    = (const float*)d_in[20];
    const float* ln3_g = (const float*)d_in[21];
    const float* ln3_b = (const float*)d_in[22];
    float* out = (float*)d_out;

    float *q, *k, *v, *ctx, *pr, *y, *ya, *ya2, *hb;
    cudaGetSymbolAddress((void**)&q,   g_q);
    cudaGetSymbolAddress((void**)&k,   g_k);
    cudaGetSymbolAddress((void**)&v,   g_v);
    cudaGetSymbolAddress((void**)&ctx, g_ctx);
    cudaGetSymbolAddress((void**)&pr,  g_pr);
    cudaGetSymbolAddress((void**)&y,   g_y);
    cudaGetSymbolAddress((void**)&ya,  g_ya);
    cudaGetSymbolAddress((void**)&ya2, g_ya2);
    cudaGetSymbolAddress((void**)&hb,  g_h);

    const dim3 blk(256);
    const dim3 gD(D_ / BN, M_ / BM);     // (4, 32)
    const dim3 gF(FF_ / BN, M_ / BM);    // (16, 32)
    const dim3 gA(S_ / 32, B_ * H_);     // (64, 16)

    // ---- stage A: causal self-attention (no out-proj) ----
    gemm_kernel<<<gD, blk>>>(x_q, sa_wq, sa_bq, q, M_, D_, D_, 2);
    gemm_kernel<<<gD, blk>>>(x_q, sa_wk, sa_bk, k, M_, D_, D_, 2);
    gemm_kernel<<<gD, blk>>>(x_q, sa_wv, sa_bv, v, M_, D_, D_, 2);
    attn_kernel<<<gA, blk>>>(q, k, v, ctx, 1);
    add_ln_kernel<<<M_, blk>>>(x_q, ctx, ln1_g, ln1_b, y);

    // ---- stage B: cross-attention with x1 ----
    gemm_kernel<<<gD, blk>>>(y,  in_w,             in_b,          q, M_, D_, D_, 2);
    gemm_kernel<<<gD, blk>>>(x1, in_w +     D_*D_, in_b +     D_, k, M_, D_, D_, 2);
    gemm_kernel<<<gD, blk>>>(x1, in_w + 2*D_*D_,   in_b + 2*D_,   v, M_, D_, D_, 2);
    attn_kernel<<<gA, blk>>>(q, k, v, ctx, 0);
    gemm_kernel<<<gD, blk>>>(ctx, out_w, out_b, pr, M_, D_, D_, 0);
    add_ln_kernel<<<M_, blk>>>(y, pr, ln2_g, ln2_b, ya);

    // ---- stage C: cross-attention with x2 (same weights) ----
    gemm_kernel<<<gD, blk>>>(ya, in_w,             in_b,          q, M_, D_, D_, 2);
    gemm_kernel<<<gD, blk>>>(x2, in_w +     D_*D_, in_b +     D_, k, M_, D_, D_, 2);
    gemm_kernel<<<gD, blk>>>(x2, in_w + 2*D_*D_,   in_b + 2*D_,   v, M_, D_, D_, 2);
    attn_kernel<<<gA, blk>>>(q, k, v, ctx, 0);
    gemm_kernel<<<gD, blk>>>(ctx, out_w, out_b, pr, M_, D_, D_, 0);
    add_ln_kernel<<<M_, blk>>>(ya, pr, ln2_g, ln2_b, ya2);

    // ---- FFN ----
    gemm_kernel<<<gF, blk>>>(ya2, w1, b1, hb, M_, FF_, D_, 1);        // relu
    gemm_kernel<<<gD, blk>>>(hb,  w2, b2, pr, M_, D_, FF_, 0);
    add_ln_kernel<<<M_, blk>>>(ya2, pr, ln3_g, ln3_b, out);
}

// round 4
// speedup vs baseline: 2.3809x; 2.3809x over previous
#include <cuda_runtime.h>

#define B_  2
#define S_  2048
#define D_  512
#define H_  8
#define DK_ 64
#define FF_ 2048
#define M_  (B_*S_)          // 4096 rows

// ---------------- scratch (no allocations allowed) ----------------
__device__ float g_q  [B_*H_*S_*DK_];
__device__ float g_k  [B_*H_*S_*DK_];
__device__ float g_v  [B_*H_*S_*DK_];
__device__ float g_ctx[M_*D_];
__device__ float g_pr [M_*D_];
__device__ float g_y  [M_*D_];
__device__ float g_ya [M_*D_];
__device__ float g_ya2[M_*D_];
__device__ float g_h  [M_*FF_];

// ---------------- generic GEMM: C[M,N] = A[M,K] @ W[N,K]^T + bias ----------------
#define BM 128
#define BN 128
#define BK 32

__global__ __launch_bounds__(256) void gemm_kernel(
    const float* __restrict__ A, const float* __restrict__ W,
    const float* __restrict__ bias, float* __restrict__ C,
    int M, int N, int K, int relu)
{
    __shared__ float As[BK][BM + 4];
    __shared__ float Bs[BK][BN + 4];

    const int tid = threadIdx.x;
    const int tx  = tid & 15;
    const int ty  = tid >> 4;
    const int m0  = blockIdx.y * BM;
    const int n0  = blockIdx.x * BN;

    float acc[8][8];
    #pragma unroll
    for (int i = 0; i < 8; ++i)
        #pragma unroll
        for (int j = 0; j < 8; ++j) acc[i][j] = 0.f;

    for (int k0 = 0; k0 < K; k0 += BK) {
        #pragma unroll
        for (int t = 0; t < 4; ++t) {
            int f = tid + t * 256;       // 0..1023
            int r = f >> 3;              // 0..127
            int c = (f & 7) << 2;        // 0,4,..,28
            float4 av = *reinterpret_cast<const float4*>(&A[(size_t)(m0 + r) * K + k0 + c]);
            As[c + 0][r] = av.x; As[c + 1][r] = av.y;
            As[c + 2][r] = av.z; As[c + 3][r] = av.w;
            float4 wv = *reinterpret_cast<const float4*>(&W[(size_t)(n0 + r) * K + k0 + c]);
            Bs[c + 0][r] = wv.x; Bs[c + 1][r] = wv.y;
            Bs[c + 2][r] = wv.z; Bs[c + 3][r] = wv.w;
        }
        __syncthreads();

        #pragma unroll 8
        for (int kk = 0; kk < BK; ++kk) {
            float a[8], b[8];
            #pragma unroll
            for (int i = 0; i < 8; ++i) a[i] = As[kk][ty * 8 + i];
            #pragma unroll
            for (int j = 0; j < 8; ++j) b[j] = Bs[kk][tx * 8 + j];
            #pragma unroll
            for (int i = 0; i < 8; ++i)
                #pragma unroll
                for (int j = 0; j < 8; ++j)
                    acc[i][j] = fmaf(a[i], b[j], acc[i][j]);
        }
        __syncthreads();
    }

    #pragma unroll
    for (int i = 0; i < 8; ++i) {
        int m = m0 + ty * 8 + i;
        #pragma unroll
        for (int j = 0; j < 8; ++j) {
            int n = n0 + tx * 8 + j;
            float val = acc[i][j] + bias[n];
            if (relu) val = fmaxf(val, 0.f);
            C[(size_t)m * N + n] = val;
        }
    }
}

// ---------------- fused QKV GEMM (M=4096, K=512, 3 x N=512), head-split out ----
__global__ __launch_bounds__(256) void qkv_kernel(
    const float* __restrict__ Aq, const float* __restrict__ Akv,
    const float* __restrict__ W0, const float* __restrict__ W1, const float* __restrict__ W2,
    const float* __restrict__ b0, const float* __restrict__ b1, const float* __restrict__ b2,
    float* __restrict__ Oq, float* __restrict__ Ok, float* __restrict__ Ov)
{
    __shared__ float As[BK][BM + 4];
    __shared__ float Bs[BK][BN + 4];

    const int w = blockIdx.x >> 2;                       // which of q/k/v
    const float* A    = (w == 0) ? Aq : Akv;
    const float* W    = (w == 0) ? W0 : (w == 1) ? W1 : W2;
    const float* bias = (w == 0) ? b0 : (w == 1) ? b1 : b2;
    float*       Out  = (w == 0) ? Oq : (w == 1) ? Ok : Ov;
    const int n0 = (blockIdx.x & 3) * BN;                // 0..384 within 512
    const int m0 = blockIdx.y * BM;

    const int tid = threadIdx.x;
    const int tx  = tid & 15;
    const int ty  = tid >> 4;

    float acc[8][8];
    #pragma unroll
    for (int i = 0; i < 8; ++i)
        #pragma unroll
        for (int j = 0; j < 8; ++j) acc[i][j] = 0.f;

    for (int k0 = 0; k0 < D_; k0 += BK) {
        #pragma unroll
        for (int t = 0; t < 4; ++t) {
            int f = tid + t * 256;
            int r = f >> 3;
            int c = (f & 7) << 2;
            float4 av = *reinterpret_cast<const float4*>(&A[(size_t)(m0 + r) * D_ + k0 + c]);
            As[c + 0][r] = av.x; As[c + 1][r] = av.y;
            As[c + 2][r] = av.z; As[c + 3][r] = av.w;
            float4 wv = *reinterpret_cast<const float4*>(&W[(size_t)(n0 + r) * D_ + k0 + c]);
            Bs[c + 0][r] = wv.x; Bs[c + 1][r] = wv.y;
            Bs[c + 2][r] = wv.z; Bs[c + 3][r] = wv.w;
        }
        __syncthreads();

        #pragma unroll 8
        for (int kk = 0; kk < BK; ++kk) {
            float a[8], b[8];
            #pragma unroll
            for (int i = 0; i < 8; ++i) a[i] = As[kk][ty * 8 + i];
            #pragma unroll
            for (int j = 0; j < 8; ++j) b[j] = Bs[kk][tx * 8 + j];
            #pragma unroll
            for (int i = 0; i < 8; ++i)
                #pragma unroll
                for (int j = 0; j < 8; ++j)
                    acc[i][j] = fmaf(a[i], b[j], acc[i][j]);
        }
        __syncthreads();
    }

    #pragma unroll
    for (int i = 0; i < 8; ++i) {
        int m = m0 + ty * 8 + i;
        int b  = m >> 11;
        int s  = m & (S_ - 1);
        #pragma unroll
        for (int j = 0; j < 8; ++j) {
            int n = n0 + tx * 8 + j;
            float val = acc[i][j] + bias[n];
            int h  = n >> 6;
            int dk = n & (DK_ - 1);
            Out[(((size_t)b * H_ + h) * S_ + s) * DK_ + dk] = val;
        }
    }
}

// ---------------- tiled flash attention ----------------
// Q,K,V: [bh][s][dk] head-split. O: merged [b][s][h*DK+dk].
// 64 query rows x 64 keys per tile; 256 threads as 16x16, 4x4 per thread.
#define BR 64
#define BC 64

__global__ __launch_bounds__(256) void attn_kernel(
    const float* __restrict__ Q, const float* __restrict__ Kg,
    const float* __restrict__ V, float* __restrict__ O, int causal)
{
    __shared__ float Qs[DK_][BR + 4];   // transposed: [dk][row]
    __shared__ float Ks[DK_][BC + 4];   // transposed: [dk][key]
    __shared__ float Vs[BC][DK_];       // natural:    [key][dk]
    __shared__ float Ps[BC][BR + 4];    // transposed: [key][row]

    const int bh  = blockIdx.y;
    const int r0  = blockIdx.x * BR;
    const int tid = threadIdx.x;
    const int tx  = tid & 15;
    const int ty  = tid >> 4;

    // load Q tile transposed (once)
    {
        const float* qb = Q + ((size_t)bh * S_ + r0) * DK_;
        #pragma unroll
        for (int t = 0; t < 4; ++t) {
            int f = tid + t * 256;       // 0..1023
            int r = f >> 4;              // 0..63
            int c = (f & 15) << 2;       // 0..60
            float4 a4 = *reinterpret_cast<const float4*>(&qb[r * DK_ + c]);
            Qs[c + 0][r] = a4.x; Qs[c + 1][r] = a4.y;
            Qs[c + 2][r] = a4.z; Qs[c + 3][r] = a4.w;
        }
    }

    float m[4], l[4], acc[4][4];
    #pragma unroll
    for (int i = 0; i < 4; ++i) {
        m[i] = -1e30f; l[i] = 0.f;
        #pragma unroll
        for (int j = 0; j < 4; ++j) acc[i][j] = 0.f;
    }

    const int kend = causal ? (r0 + BR) : S_;
    for (int kt = 0; kt < kend; kt += BC) {
        __syncthreads();   // previous tile's Ps/Vs reads complete
        {
            const float* kb = Kg + ((size_t)bh * S_ + kt) * DK_;
            const float* vb = V  + ((size_t)bh * S_ + kt) * DK_;
            #pragma unroll
            for (int t = 0; t < 4; ++t) {
                int f = tid + t * 256;
                int r = f >> 4;
                int c = (f & 15) << 2;
                float4 a4 = *reinterpret_cast<const float4*>(&kb[r * DK_ + c]);
                Ks[c + 0][r] = a4.x; Ks[c + 1][r] = a4.y;
                Ks[c + 2][r] = a4.z; Ks[c + 3][r] = a4.w;
                *reinterpret_cast<float4*>(&Vs[r][c]) =
                    *reinterpret_cast<const float4*>(&vb[r * DK_ + c]);
            }
        }
        __syncthreads();

        // ---- S = Q @ K^T (64x64x64) ----
        float s[4][4];
        #pragma unroll
        for (int i = 0; i < 4; ++i)
            #pragma unroll
            for (int j = 0; j < 4; ++j) s[i][j] = 0.f;

        #pragma unroll 8
        for (int kk = 0; kk < DK_; ++kk) {
            float4 a = *reinterpret_cast<const float4*>(&Qs[kk][ty * 4]);
            float4 b = *reinterpret_cast<const float4*>(&Ks[kk][tx * 4]);
            float av[4] = {a.x, a.y, a.z, a.w};
            float bv[4] = {b.x, b.y, b.z, b.w};
            #pragma unroll
            for (int i = 0; i < 4; ++i)
                #pragma unroll
                for (int j = 0; j < 4; ++j)
                    s[i][j] = fmaf(av[i], bv[j], s[i][j]);
        }

        // scale + causal mask (only diagonal tile needs it)
        const bool dmask = (causal && kt == r0);
        #pragma unroll
        for (int i = 0; i < 4; ++i)
            #pragma unroll
            for (int j = 0; j < 4; ++j) {
                float v = s[i][j] * 0.125f;
                if (dmask && (kt + tx * 4 + j) > (r0 + ty * 4 + i)) v = -1e30f;
                s[i][j] = v;
            }

        // ---- online softmax per row (rows spread over tx lanes) ----
        #pragma unroll
        for (int i = 0; i < 4; ++i) {
            float mr = fmaxf(fmaxf(s[i][0], s[i][1]), fmaxf(s[i][2], s[i][3]));
            mr = fmaxf(mr, __shfl_xor_sync(0xffffffffu, mr, 1));
            mr = fmaxf(mr, __shfl_xor_sync(0xffffffffu, mr, 2));
            mr = fmaxf(mr, __shfl_xor_sync(0xffffffffu, mr, 4));
            mr = fmaxf(mr, __shfl_xor_sync(0xffffffffu, mr, 8));
            float nm   = fmaxf(m[i], mr);
            float corr = __expf(m[i] - nm);
            m[i] = nm;
            float rs = 0.f;
            #pragma unroll
            for (int j = 0; j < 4; ++j) {
                s[i][j] = __expf(s[i][j] - nm);
                rs += s[i][j];
            }
            rs += __shfl_xor_sync(0xffffffffu, rs, 1);
            rs += __shfl_xor_sync(0xffffffffu, rs, 2);
            rs += __shfl_xor_sync(0xffffffffu, rs, 4);
            rs += __shfl_xor_sync(0xffffffffu, rs, 8);
            l[i] = l[i] * corr + rs;
            #pragma unroll
            for (int j = 0; j < 4; ++j) acc[i][j] *= corr;
        }

        // store P transposed: Ps[key][row]
        #pragma unroll
        for (int j = 0; j < 4; ++j) {
            *reinterpret_cast<float4*>(&Ps[tx * 4 + j][ty * 4]) =
                make_float4(s[0][j], s[1][j], s[2][j], s[3][j]);
        }
        __syncthreads();

        // ---- O += P @ V (64x64x64) ----
        #pragma unroll 8
        for (int kk = 0; kk < BC; ++kk) {
            float4 a = *reinterpret_cast<const float4*>(&Ps[kk][ty * 4]);
            float4 b = *reinterpret_cast<const float4*>(&Vs[kk][tx * 4]);
            float av[4] = {a.x, a.y, a.z, a.w};
            float bv[4] = {b.x, b.y, b.z, b.w};
            #pragma unroll
            for (int i = 0; i < 4; ++i)
                #pragma unroll
                for (int j = 0; j < 4; ++j)
                    acc[i][j] = fmaf(av[i], bv[j], acc[i][j]);
        }
    }

    // epilogue: merged layout
    const int b = bh >> 3, h = bh & 7;
    #pragma unroll
    for (int i = 0; i < 4; ++i) {
        float inv = 1.f / l[i];
        float4 o4 = make_float4(acc[i][0] * inv, acc[i][1] * inv,
                                acc[i][2] * inv, acc[i][3] * inv);
        *reinterpret_cast<float4*>(
            &O[((size_t)(b * S_ + r0 + ty * 4 + i)) * D_ + h * DK_ + tx * 4]) = o4;
    }
}

// ---------------- fused residual-add + LayerNorm ----------------
__global__ __launch_bounds__(256) void add_ln_kernel(
    const float* __restrict__ X, const float* __restrict__ Y,
    const float* __restrict__ gam, const float* __restrict__ bet,
    float* __restrict__ O)
{
    __shared__ float sh_s[8], sh_q[8];
    const int row = blockIdx.x;
    const int tid = threadIdx.x;
    const float* xp = X + (size_t)row * D_;
    const float* yp = Y + (size_t)row * D_;

    float v0 = xp[tid] + yp[tid];
    float v1 = xp[tid + 256] + yp[tid + 256];
    float s  = v0 + v1;
    float qq = v0 * v0 + v1 * v1;
    #pragma unroll
    for (int o = 16; o; o >>= 1) {
        s  += __shfl_xor_sync(0xffffffffu, s, o);
        qq += __shfl_xor_sync(0xffffffffu, qq, o);
    }
    if ((tid & 31) == 0) { sh_s[tid >> 5] = s; sh_q[tid >> 5] = qq; }
    __syncthreads();
    if (tid < 32) {
        float s2 = (tid < 8) ? sh_s[tid] : 0.f;
        float q2 = (tid < 8) ? sh_q[tid] : 0.f;
        #pragma unroll
        for (int o = 4; o; o >>= 1) {
            s2 += __shfl_xor_sync(0xffffffffu, s2, o);
            q2 += __shfl_xor_sync(0xffffffffu, q2, o);
        }
        if (tid == 0) { sh_s[0] = s2; sh_q[0] = q2; }
    }
    __syncthreads();

    const float mu  = sh_s[0] * (1.f / 512.f);
    const float var = sh_q[0] * (1.f / 512.f) - mu * mu;
    const float inv = rsqrtf(var + 1e-5f);
    O[(size_t)row * D_ + tid]       = (v0 - mu) * inv * gam[tid]       + bet[tid];
    O[(size_t)row * D_ + tid + 256] = (v1 - mu) * inv * gam[tid + 256] + bet[tid + 256];
}

// ---------------- orchestration ----------------
extern "C" void kernel_launch(void* const* d_in, const int* in_sizes, int n_in,
                              void* d_out, int out_size)
{
    const float* x_q   = (const float*)d_in[0];
    const float* x1    = (const float*)d_in[1];
    const float* x2    = (const float*)d_in[2];
    const float* sa_wq = (const float*)d_in[3];
    const float* sa_bq = (const float*)d_in[4];
    const float* sa_wk = (const float*)d_in[5];
    const float* sa_bk = (const float*)d_in[6];
    const float* sa_wv = (const float*)d_in[7];
    const float* sa_bv = (const float*)d_in[8];
    const float* ln1_g = (const float*)d_in[9];
    const float* ln1_b = (const float*)d_in[10];
    const float* in_w  = (const float*)d_in[11];
    const float* in_b  = (const float*)d_in[12];
    const float* out_w = (const float*)d_in[13];
    const float* out_b = (const float*)d_in[14];
    const float* ln2_g = (const float*)d_in[15];
    const float* ln2_b = (const float*)d_in[16];
    const float* w1    = (const float*)d_in[17];
    const float* b1    = (const float*)d_in[18];
    const float* w2    = (const float*)d_in[19];
    const float* b2    = (const float*)d_in[20];
    const float* ln3_g = (const float*)d_in[21];
    const float* ln3_b = (const float*)d_in[22];
    float* out = (float*)d_out;

    float *q, *k, *v, *ctx, *pr, *y, *ya, *ya2, *hb;
    cudaGetSymbolAddress((void**)&q,   g_q);
    cudaGetSymbolAddress((void**)&k,   g_k);
    cudaGetSymbolAddress((void**)&v,   g_v);
    cudaGetSymbolAddress((void**)&ctx, g_ctx);
    cudaGetSymbolAddress((void**)&pr,  g_pr);
    cudaGetSymbolAddress((void**)&y,   g_y);
    cudaGetSymbolAddress((void**)&ya,  g_ya);
    cudaGetSymbolAddress((void**)&ya2, g_ya2);
    cudaGetSymbolAddress((void**)&hb,  g_h);

    const dim3 blk(256);
    const dim3 gQKV(12, M_ / BM);        // (12, 32)
    const dim3 gD(D_ / BN, M_ / BM);     // (4, 32)
    const dim3 gF(FF_ / BN, M_ / BM);    // (16, 32)
    const dim3 gA(S_ / BR, B_ * H_);     // (32, 16)

    // ---- stage A: causal self-attention (no out-proj) ----
    qkv_kernel<<<gQKV, blk>>>(x_q, x_q, sa_wq, sa_wk, sa_wv,
                              sa_bq, sa_bk, sa_bv, q, k, v);
    attn_kernel<<<gA, blk>>>(q, k, v, ctx, 1);
    add_ln_kernel<<<M_, blk>>>(x_q, ctx, ln1_g, ln1_b, y);

    // ---- stage B: cross-attention with x1 ----
    qkv_kernel<<<gQKV, blk>>>(y, x1, in_w, in_w + D_*D_, in_w + 2*D_*D_,
                              in_b, in_b + D_, in_b + 2*D_, q, k, v);
    attn_kernel<<<gA, blk>>>(q, k, v, ctx, 0);
    gemm_kernel<<<gD, blk>>>(ctx, out_w, out_b, pr, M_, D_, D_, 0);
    add_ln_kernel<<<M_, blk>>>(y, pr, ln2_g, ln2_b, ya);

    // ---- stage C: cross-attention with x2 (same weights) ----
    qkv_kernel<<<gQKV, blk>>>(ya, x2, in_w, in_w + D_*D_, in_w + 2*D_*D_,
                              in_b, in_b + D_, in_b + 2*D_, q, k, v);
    attn_kernel<<<gA, blk>>>(q, k, v, ctx, 0);
    gemm_kernel<<<gD, blk>>>(ctx, out_w, out_b, pr, M_, D_, D_, 0);
    add_ln_kernel<<<M_, blk>>>(ya, pr, ln2_g, ln2_b, ya2);

    // ---- FFN ----
    gemm_kernel<<<gF, blk>>>(ya2, w1, b1, hb, M_, FF_, D_, 1);
    gemm_kernel<<<gD, blk>>>(hb,  w2, b2, pr, M_, D_, FF_, 0);
    add_ln_kernel<<<M_, blk>>>(ya2, pr, ln3_g, ln3_b, out);
}

// round 5
// speedup vs baseline: 2.3862x; 1.0022x over previous
#include <cuda_runtime.h>

#define B_  2
#define S_  2048
#define D_  512
#define H_  8
#define DK_ 64
#define FF_ 2048
#define M_  (B_*S_)          // 4096 rows

// ---------------- scratch (no allocations allowed) ----------------
__device__ float g_q  [B_*H_*S_*DK_];
__device__ float g_k  [B_*H_*S_*DK_];
__device__ float g_v  [B_*H_*S_*DK_];
__device__ float g_ctx[M_*D_];
__device__ float g_pr [M_*D_];
__device__ float g_y  [M_*D_];
__device__ float g_ya [M_*D_];
__device__ float g_ya2[M_*D_];
__device__ float g_h  [M_*FF_];

// ---------------- generic GEMM: C[M,N] = A[M,K] @ W[N,K]^T + bias ----------------
#define BM 128
#define BN 128
#define BK 32

__global__ __launch_bounds__(256) void gemm_kernel(
    const float* __restrict__ A, const float* __restrict__ W,
    const float* __restrict__ bias, float* __restrict__ C,
    int M, int N, int K, int relu)
{
    __shared__ float As[BK][BM + 4];
    __shared__ float Bs[BK][BN + 4];

    const int tid = threadIdx.x;
    const int tx  = tid & 15;
    const int ty  = tid >> 4;
    const int m0  = blockIdx.y * BM;
    const int n0  = blockIdx.x * BN;

    float acc[8][8];
    #pragma unroll
    for (int i = 0; i < 8; ++i)
        #pragma unroll
        for (int j = 0; j < 8; ++j) acc[i][j] = 0.f;

    for (int k0 = 0; k0 < K; k0 += BK) {
        #pragma unroll
        for (int t = 0; t < 4; ++t) {
            int f = tid + t * 256;       // 0..1023
            int r = f >> 3;              // 0..127
            int c = (f & 7) << 2;        // 0,4,..,28
            float4 av = *reinterpret_cast<const float4*>(&A[(size_t)(m0 + r) * K + k0 + c]);
            As[c + 0][r] = av.x; As[c + 1][r] = av.y;
            As[c + 2][r] = av.z; As[c + 3][r] = av.w;
            float4 wv = *reinterpret_cast<const float4*>(&W[(size_t)(n0 + r) * K + k0 + c]);
            Bs[c + 0][r] = wv.x; Bs[c + 1][r] = wv.y;
            Bs[c + 2][r] = wv.z; Bs[c + 3][r] = wv.w;
        }
        __syncthreads();

        #pragma unroll 8
        for (int kk = 0; kk < BK; ++kk) {
            float a[8], b[8];
            #pragma unroll
            for (int i = 0; i < 8; ++i) a[i] = As[kk][ty * 8 + i];
            #pragma unroll
            for (int j = 0; j < 8; ++j) b[j] = Bs[kk][tx * 8 + j];
            #pragma unroll
            for (int i = 0; i < 8; ++i)
                #pragma unroll
                for (int j = 0; j < 8; ++j)
                    acc[i][j] = fmaf(a[i], b[j], acc[i][j]);
        }
        __syncthreads();
    }

    #pragma unroll
    for (int i = 0; i < 8; ++i) {
        int m = m0 + ty * 8 + i;
        #pragma unroll
        for (int j = 0; j < 8; ++j) {
            int n = n0 + tx * 8 + j;
            float val = acc[i][j] + bias[n];
            if (relu) val = fmaxf(val, 0.f);
            C[(size_t)m * N + n] = val;
        }
    }
}

// ---------------- fused QKV GEMM (M=4096, K=512, 3 x N=512), head-split out ----
__global__ __launch_bounds__(256) void qkv_kernel(
    const float* __restrict__ Aq, const float* __restrict__ Akv,
    const float* __restrict__ W0, const float* __restrict__ W1, const float* __restrict__ W2,
    const float* __restrict__ b0, const float* __restrict__ b1, const float* __restrict__ b2,
    float* __restrict__ Oq, float* __restrict__ Ok, float* __restrict__ Ov)
{
    __shared__ float As[BK][BM + 4];
    __shared__ float Bs[BK][BN + 4];

    const int w = blockIdx.x >> 2;                       // which of q/k/v
    const float* A    = (w == 0) ? Aq : Akv;
    const float* W    = (w == 0) ? W0 : (w == 1) ? W1 : W2;
    const float* bias = (w == 0) ? b0 : (w == 1) ? b1 : b2;
    float*       Out  = (w == 0) ? Oq : (w == 1) ? Ok : Ov;
    const int n0 = (blockIdx.x & 3) * BN;                // 0..384 within 512
    const int m0 = blockIdx.y * BM;

    const int tid = threadIdx.x;
    const int tx  = tid & 15;
    const int ty  = tid >> 4;

    float acc[8][8];
    #pragma unroll
    for (int i = 0; i < 8; ++i)
        #pragma unroll
        for (int j = 0; j < 8; ++j) acc[i][j] = 0.f;

    for (int k0 = 0; k0 < D_; k0 += BK) {
        #pragma unroll
        for (int t = 0; t < 4; ++t) {
            int f = tid + t * 256;
            int r = f >> 3;
            int c = (f & 7) << 2;
            float4 av = *reinterpret_cast<const float4*>(&A[(size_t)(m0 + r) * D_ + k0 + c]);
            As[c + 0][r] = av.x; As[c + 1][r] = av.y;
            As[c + 2][r] = av.z; As[c + 3][r] = av.w;
            float4 wv = *reinterpret_cast<const float4*>(&W[(size_t)(n0 + r) * D_ + k0 + c]);
            Bs[c + 0][r] = wv.x; Bs[c + 1][r] = wv.y;
            Bs[c + 2][r] = wv.z; Bs[c + 3][r] = wv.w;
        }
        __syncthreads();

        #pragma unroll 8
        for (int kk = 0; kk < BK; ++kk) {
            float a[8], b[8];
            #pragma unroll
            for (int i = 0; i < 8; ++i) a[i] = As[kk][ty * 8 + i];
            #pragma unroll
            for (int j = 0; j < 8; ++j) b[j] = Bs[kk][tx * 8 + j];
            #pragma unroll
            for (int i = 0; i < 8; ++i)
                #pragma unroll
                for (int j = 0; j < 8; ++j)
                    acc[i][j] = fmaf(a[i], b[j], acc[i][j]);
        }
        __syncthreads();
    }

    #pragma unroll
    for (int i = 0; i < 8; ++i) {
        int m = m0 + ty * 8 + i;
        int b  = m >> 11;
        int s  = m & (S_ - 1);
        #pragma unroll
        for (int j = 0; j < 8; ++j) {
            int n = n0 + tx * 8 + j;
            float val = acc[i][j] + bias[n];
            int h  = n >> 6;
            int dk = n & (DK_ - 1);
            Out[(((size_t)b * H_ + h) * S_ + s) * DK_ + dk] = val;
        }
    }
}

// ---------------- tiled flash attention ----------------
// Q,K,V: [bh][s][dk] head-split. O: merged [b][s][h*DK+dk].
// 64 query rows x 64 keys per tile; 256 threads as 16x16, 4x4 per thread.
#define BR 64
#define BC 64

__global__ __launch_bounds__(256) void attn_kernel(
    const float* __restrict__ Q, const float* __restrict__ Kg,
    const float* __restrict__ V, float* __restrict__ O, int causal)
{
    __shared__ float Qs[DK_][BR + 4];   // transposed: [dk][row]
    __shared__ float Ks[DK_][BC + 4];   // transposed: [dk][key]
    __shared__ float Vs[BC][DK_];       // natural:    [key][dk]
    __shared__ float Ps[BC][BR + 4];    // transposed: [key][row]

    const int bh  = blockIdx.y;
    const int r0  = blockIdx.x * BR;
    const int tid = threadIdx.x;
    const int tx  = tid & 15;
    const int ty  = tid >> 4;

    // load Q tile transposed (once)
    {
        const float* qb = Q + ((size_t)bh * S_ + r0) * DK_;
        #pragma unroll
        for (int t = 0; t < 4; ++t) {
            int f = tid + t * 256;       // 0..1023
            int r = f >> 4;              // 0..63
            int c = (f & 15) << 2;       // 0..60
            float4 a4 = *reinterpret_cast<const float4*>(&qb[r * DK_ + c]);
            Qs[c + 0][r] = a4.x; Qs[c + 1][r] = a4.y;
            Qs[c + 2][r] = a4.z; Qs[c + 3][r] = a4.w;
        }
    }

    float m[4], l[4], acc[4][4];
    #pragma unroll
    for (int i = 0; i < 4; ++i) {
        m[i] = -1e30f; l[i] = 0.f;
        #pragma unroll
        for (int j = 0; j < 4; ++j) acc[i][j] = 0.f;
    }

    const int kend = causal ? (r0 + BR) : S_;
    for (int kt = 0; kt < kend; kt += BC) {
        __syncthreads();   // previous tile's Ps/Vs reads complete
        {
            const float* kb = Kg + ((size_t)bh * S_ + kt) * DK_;
            const float* vb = V  + ((size_t)bh * S_ + kt) * DK_;
            #pragma unroll
            for (int t = 0; t < 4; ++t) {
                int f = tid + t * 256;
                int r = f >> 4;
                int c = (f & 15) << 2;
                float4 a4 = *reinterpret_cast<const float4*>(&kb[r * DK_ + c]);
                Ks[c + 0][r] = a4.x; Ks[c + 1][r] = a4.y;
                Ks[c + 2][r] = a4.z; Ks[c + 3][r] = a4.w;
                *reinterpret_cast<float4*>(&Vs[r][c]) =
                    *reinterpret_cast<const float4*>(&vb[r * DK_ + c]);
            }
        }
        __syncthreads();

        // ---- S = Q @ K^T (64x64x64) ----
        float s[4][4];
        #pragma unroll
        for (int i = 0; i < 4; ++i)
            #pragma unroll
            for (int j = 0; j < 4; ++j) s[i][j] = 0.f;

        #pragma unroll 8
        for (int kk = 0; kk < DK_; ++kk) {
            float4 a = *reinterpret_cast<const float4*>(&Qs[kk][ty * 4]);
            float4 b = *reinterpret_cast<const float4*>(&Ks[kk][tx * 4]);
            float av[4] = {a.x, a.y, a.z, a.w};
            float bv[4] = {b.x, b.y, b.z, b.w};
            #pragma unroll
            for (int i = 0; i < 4; ++i)
                #pragma unroll
                for (int j = 0; j < 4; ++j)
                    s[i][j] = fmaf(av[i], bv[j], s[i][j]);
        }

        // scale + causal mask (only diagonal tile needs it)
        const bool dmask = (causal && kt == r0);
        #pragma unroll
        for (int i = 0; i < 4; ++i)
            #pragma unroll
            for (int j = 0; j < 4; ++j) {
                float v = s[i][j] * 0.125f;
                if (dmask && (kt + tx * 4 + j) > (r0 + ty * 4 + i)) v = -1e30f;
                s[i][j] = v;
            }

        // ---- online softmax per row (rows spread over tx lanes) ----
        #pragma unroll
        for (int i = 0; i < 4; ++i) {
            float mr = fmaxf(fmaxf(s[i][0], s[i][1]), fmaxf(s[i][2], s[i][3]));
            mr = fmaxf(mr, __shfl_xor_sync(0xffffffffu, mr, 1));
            mr = fmaxf(mr, __shfl_xor_sync(0xffffffffu, mr, 2));
            mr = fmaxf(mr, __shfl_xor_sync(0xffffffffu, mr, 4));
            mr = fmaxf(mr, __shfl_xor_sync(0xffffffffu, mr, 8));
            float nm   = fmaxf(m[i], mr);
            float corr = __expf(m[i] - nm);
            m[i] = nm;
            float rs = 0.f;
            #pragma unroll
            for (int j = 0; j < 4; ++j) {
                s[i][j] = __expf(s[i][j] - nm);
                rs += s[i][j];
            }
            rs += __shfl_xor_sync(0xffffffffu, rs, 1);
            rs += __shfl_xor_sync(0xffffffffu, rs, 2);
            rs += __shfl_xor_sync(0xffffffffu, rs, 4);
            rs += __shfl_xor_sync(0xffffffffu, rs, 8);
            l[i] = l[i] * corr + rs;
            #pragma unroll
            for (int j = 0; j < 4; ++j) acc[i][j] *= corr;
        }

        // store P transposed: Ps[key][row]
        #pragma unroll
        for (int j = 0; j < 4; ++j) {
            *reinterpret_cast<float4*>(&Ps[tx * 4 + j][ty * 4]) =
                make_float4(s[0][j], s[1][j], s[2][j], s[3][j]);
        }
        __syncthreads();

        // ---- O += P @ V (64x64x64) ----
        #pragma unroll 8
        for (int kk = 0; kk < BC; ++kk) {
            float4 a = *reinterpret_cast<const float4*>(&Ps[kk][ty * 4]);
            float4 b = *reinterpret_cast<const float4*>(&Vs[kk][tx * 4]);
            float av[4] = {a.x, a.y, a.z, a.w};
            float bv[4] = {b.x, b.y, b.z, b.w};
            #pragma unroll
            for (int i = 0; i < 4; ++i)
                #pragma unroll
                for (int j = 0; j < 4; ++j)
                    acc[i][j] = fmaf(av[i], bv[j], acc[i][j]);
        }
    }

    // epilogue: merged layout
    const int b = bh >> 3, h = bh & 7;
    #pragma unroll
    for (int i = 0; i < 4; ++i) {
        float inv = 1.f / l[i];
        float4 o4 = make_float4(acc[i][0] * inv, acc[i][1] * inv,
                                acc[i][2] * inv, acc[i][3] * inv);
        *reinterpret_cast<float4*>(
            &O[((size_t)(b * S_ + r0 + ty * 4 + i)) * D_ + h * DK_ + tx * 4]) = o4;
    }
}

// ---------------- fused residual-add + LayerNorm ----------------
__global__ __launch_bounds__(256) void add_ln_kernel(
    const float* __restrict__ X, const float* __restrict__ Y,
    const float* __restrict__ gam, const float* __restrict__ bet,
    float* __restrict__ O)
{
    __shared__ float sh_s[8], sh_q[8];
    const int row = blockIdx.x;
    const int tid = threadIdx.x;
    const float* xp = X + (size_t)row * D_;
    const float* yp = Y + (size_t)row * D_;

    float v0 = xp[tid] + yp[tid];
    float v1 = xp[tid + 256] + yp[tid + 256];
    float s  = v0 + v1;
    float qq = v0 * v0 + v1 * v1;
    #pragma unroll
    for (int o = 16; o; o >>= 1) {
        s  += __shfl_xor_sync(0xffffffffu, s, o);
        qq += __shfl_xor_sync(0xffffffffu, qq, o);
    }
    if ((tid & 31) == 0) { sh_s[tid >> 5] = s; sh_q[tid >> 5] = qq; }
    __syncthreads();
    if (tid < 32) {
        float s2 = (tid < 8) ? sh_s[tid] : 0.f;
        float q2 = (tid < 8) ? sh_q[tid] : 0.f;
        #pragma unroll
        for (int o = 4; o; o >>= 1) {
            s2 += __shfl_xor_sync(0xffffffffu, s2, o);
            q2 += __shfl_xor_sync(0xffffffffu, q2, o);
        }
        if (tid == 0) { sh_s[0] = s2; sh_q[0] = q2; }
    }
    __syncthreads();

    const float mu  = sh_s[0] * (1.f / 512.f);
    const float var = sh_q[0] * (1.f / 512.f) - mu * mu;
    const float inv = rsqrtf(var + 1e-5f);
    O[(size_t)row * D_ + tid]       = (v0 - mu) * inv * gam[tid]       + bet[tid];
    O[(size_t)row * D_ + tid + 256] = (v1 - mu) * inv * gam[tid + 256] + bet[tid + 256];
}

// ---------------- orchestration ----------------
extern "C" void kernel_launch(void* const* d_in, const int* in_sizes, int n_in,
                              void* d_out, int out_size)
{
    const float* x_q   = (const float*)d_in[0];
    const float* x1    = (const float*)d_in[1];
    const float* x2    = (const float*)d_in[2];
    const float* sa_wq = (const float*)d_in[3];
    const float* sa_bq = (const float*)d_in[4];
    const float* sa_wk = (const float*)d_in[5];
    const float* sa_bk = (const float*)d_in[6];
    const float* sa_wv = (const float*)d_in[7];
    const float* sa_bv = (const float*)d_in[8];
    const float* ln1_g = (const float*)d_in[9];
    const float* ln1_b = (const float*)d_in[10];
    const float* in_w  = (const float*)d_in[11];
    const float* in_b  = (const float*)d_in[12];
    const float* out_w = (const float*)d_in[13];
    const float* out_b = (const float*)d_in[14];
    const float* ln2_g = (const float*)d_in[15];
    const float* ln2_b = (const float*)d_in[16];
    const float* w1    = (const float*)d_in[17];
    const float* b1    = (const float*)d_in[18];
    const float* w2    = (const float*)d_in[19];
    const float* b2    = (const float*)d_in[20];
    const float* ln3_g = (const float*)d_in[21];
    const float* ln3_b = (const float*)d_in[22];
    float* out = (float*)d_out;

    float *q, *k, *v, *ctx, *pr, *y, *ya, *ya2, *hb;
    cudaGetSymbolAddress((void**)&q,   g_q);
    cudaGetSymbolAddress((void**)&k,   g_k);
    cudaGetSymbolAddress((void**)&v,   g_v);
    cudaGetSymbolAddress((void**)&ctx, g_ctx);
    cudaGetSymbolAddress((void**)&pr,  g_pr);
    cudaGetSymbolAddress((void**)&y,   g_y);
    cudaGetSymbolAddress((void**)&ya,  g_ya);
    cudaGetSymbolAddress((void**)&ya2, g_ya2);
    cudaGetSymbolAddress((void**)&hb,  g_h);

    const dim3 blk(256);
    const dim3 gQKV(12, M_ / BM);        // (12, 32)
    const dim3 gD(D_ / BN, M_ / BM);     // (4, 32)
    const dim3 gF(FF_ / BN, M_ / BM);    // (16, 32)
    const dim3 gA(S_ / BR, B_ * H_);     // (32, 16)

    // ---- stage A: causal self-attention (no out-proj) ----
    qkv_kernel<<<gQKV, blk>>>(x_q, x_q, sa_wq, sa_wk, sa_wv,
                              sa_bq, sa_bk, sa_bv, q, k, v);
    attn_kernel<<<gA, blk>>>(q, k, v, ctx, 1);
    add_ln_kernel<<<M_, blk>>>(x_q, ctx, ln1_g, ln1_b, y);

    // ---- stage B: cross-attention with x1 ----
    qkv_kernel<<<gQKV, blk>>>(y, x1, in_w, in_w + D_*D_, in_w + 2*D_*D_,
                              in_b, in_b + D_, in_b + 2*D_, q, k, v);
    attn_kernel<<<gA, blk>>>(q, k, v, ctx, 0);
    gemm_kernel<<<gD, blk>>>(ctx, out_w, out_b, pr, M_, D_, D_, 0);
    add_ln_kernel<<<M_, blk>>>(y, pr, ln2_g, ln2_b, ya);

    // ---- stage C: cross-attention with x2 (same weights) ----
    qkv_kernel<<<gQKV, blk>>>(ya, x2, in_w, in_w + D_*D_, in_w + 2*D_*D_,
                              in_b, in_b + D_, in_b + 2*D_, q, k, v);
    attn_kernel<<<gA, blk>>>(q, k, v, ctx, 0);
    gemm_kernel<<<gD, blk>>>(ctx, out_w, out_b, pr, M_, D_, D_, 0);
    add_ln_kernel<<<M_, blk>>>(ya, pr, ln2_g, ln2_b, ya2);

    // ---- FFN ----
    gemm_kernel<<<gF, blk>>>(ya2, w1, b1, hb, M_, FF_, D_, 1);
    gemm_kernel<<<gD, blk>>>(hb,  w2, b2, pr, M_, D_, FF_, 0);
    add_ln_kernel<<<M_, blk>>>(ya2, pr, ln3_g, ln3_b, out);
}

// round 6
// speedup vs baseline: 2.4863x; 1.0419x over previous
#include <cuda_runtime.h>

#define B_  2
#define S_  2048
#define D_  512
#define H_  8
#define DK_ 64
#define FF_ 2048
#define M_  (B_*S_)          // 4096 rows

// ---------------- f32x2 packed helpers (sm_103a FFMA2 path) ----------------
__device__ __forceinline__ unsigned long long dup2(float x) {
    unsigned long long r;
    asm("mov.b64 %0, {%1, %1};" : "=l"(r) : "f"(x));
    return r;
}
__device__ __forceinline__ void ffma2(unsigned long long& d,
                                      unsigned long long a,
                                      unsigned long long b) {
    asm("fma.rn.f32x2 %0, %1, %2, %0;" : "+l"(d) : "l"(a), "l"(b));
}
__device__ __forceinline__ void fmul2(unsigned long long& d, unsigned long long a) {
    asm("mul.rn.f32x2 %0, %0, %1;" : "+l"(d) : "l"(a));
}
__device__ __forceinline__ float2 unpack2(unsigned long long v) {
    float2 f;
    asm("mov.b64 {%0, %1}, %2;" : "=f"(f.x), "=f"(f.y) : "l"(v));
    return f;
}

// ---------------- scratch (no allocations allowed) ----------------
__device__ float g_q  [B_*H_*S_*DK_];
__device__ float g_k  [B_*H_*S_*DK_];
__device__ float g_v  [B_*H_*S_*DK_];
__device__ float g_ctx[M_*D_];
__device__ float g_pr [M_*D_];
__device__ float g_y  [M_*D_];
__device__ float g_ya [M_*D_];
__device__ float g_ya2[M_*D_];
__device__ float g_h  [M_*FF_];

// ---------------- generic GEMM: C[M,N] = A[M,K] @ W[N,K]^T + bias ----------------
#define BM 128
#define BN 128
#define BK 32

__global__ __launch_bounds__(256) void gemm_kernel(
    const float* __restrict__ A, const float* __restrict__ W,
    const float* __restrict__ bias, float* __restrict__ C,
    int M, int N, int K, int relu)
{
    __shared__ float As[BK][BM + 4];
    __shared__ float Bs[BK][BN + 4];

    const int tid = threadIdx.x;
    const int tx  = tid & 15;
    const int ty  = tid >> 4;
    const int m0  = blockIdx.y * BM;
    const int n0  = blockIdx.x * BN;

    unsigned long long acc[8][4];   // rows i=0..7, column-pairs jp=0..3
    #pragma unroll
    for (int i = 0; i < 8; ++i)
        #pragma unroll
        for (int j = 0; j < 4; ++j) acc[i][j] = 0ull;

    for (int k0 = 0; k0 < K; k0 += BK) {
        #pragma unroll
        for (int t = 0; t < 4; ++t) {
            int f = tid + t * 256;       // 0..1023
            int r = f >> 3;              // 0..127
            int c = (f & 7) << 2;        // 0,4,..,28
            float4 av = *reinterpret_cast<const float4*>(&A[(size_t)(m0 + r) * K + k0 + c]);
            As[c + 0][r] = av.x; As[c + 1][r] = av.y;
            As[c + 2][r] = av.z; As[c + 3][r] = av.w;
            float4 wv = *reinterpret_cast<const float4*>(&W[(size_t)(n0 + r) * K + k0 + c]);
            Bs[c + 0][r] = wv.x; Bs[c + 1][r] = wv.y;
            Bs[c + 2][r] = wv.z; Bs[c + 3][r] = wv.w;
        }
        __syncthreads();

        #pragma unroll 8
        for (int kk = 0; kk < BK; ++kk) {
            float4 a0 = *reinterpret_cast<const float4*>(&As[kk][ty * 8]);
            float4 a1 = *reinterpret_cast<const float4*>(&As[kk][ty * 8 + 4]);
            ulonglong2 bp0 = *reinterpret_cast<const ulonglong2*>(&Bs[kk][tx * 8]);
            ulonglong2 bp1 = *reinterpret_cast<const ulonglong2*>(&Bs[kk][tx * 8 + 4]);
            unsigned long long bv[4] = {bp0.x, bp0.y, bp1.x, bp1.y};
            float av[8] = {a0.x, a0.y, a0.z, a0.w, a1.x, a1.y, a1.z, a1.w};
            #pragma unroll
            for (int i = 0; i < 8; ++i) {
                unsigned long long aa = dup2(av[i]);
                #pragma unroll
                for (int j = 0; j < 4; ++j) ffma2(acc[i][j], aa, bv[j]);
            }
        }
        __syncthreads();
    }

    #pragma unroll
    for (int i = 0; i < 8; ++i) {
        int m = m0 + ty * 8 + i;
        #pragma unroll
        for (int j = 0; j < 4; ++j) {
            int n = n0 + tx * 8 + j * 2;
            float2 f = unpack2(acc[i][j]);
            float v0 = f.x + bias[n];
            float v1 = f.y + bias[n + 1];
            if (relu) { v0 = fmaxf(v0, 0.f); v1 = fmaxf(v1, 0.f); }
            C[(size_t)m * N + n]     = v0;
            C[(size_t)m * N + n + 1] = v1;
        }
    }
}

// ---------------- fused QKV GEMM (M=4096, K=512, 3 x N=512), head-split out ----
__global__ __launch_bounds__(256) void qkv_kernel(
    const float* __restrict__ Aq, const float* __restrict__ Akv,
    const float* __restrict__ W0, const float* __restrict__ W1, const float* __restrict__ W2,
    const float* __restrict__ b0, const float* __restrict__ b1, const float* __restrict__ b2,
    float* __restrict__ Oq, float* __restrict__ Ok, float* __restrict__ Ov)
{
    __shared__ float As[BK][BM + 4];
    __shared__ float Bs[BK][BN + 4];

    const int w = blockIdx.x >> 2;
    const float* A    = (w == 0) ? Aq : Akv;
    const float* W    = (w == 0) ? W0 : (w == 1) ? W1 : W2;
    const float* bias = (w == 0) ? b0 : (w == 1) ? b1 : b2;
    float*       Out  = (w == 0) ? Oq : (w == 1) ? Ok : Ov;
    const int n0 = (blockIdx.x & 3) * BN;
    const int m0 = blockIdx.y * BM;

    const int tid = threadIdx.x;
    const int tx  = tid & 15;
    const int ty  = tid >> 4;

    unsigned long long acc[8][4];
    #pragma unroll
    for (int i = 0; i < 8; ++i)
        #pragma unroll
        for (int j = 0; j < 4; ++j) acc[i][j] = 0ull;

    for (int k0 = 0; k0 < D_; k0 += BK) {
        #pragma unroll
        for (int t = 0; t < 4; ++t) {
            int f = tid + t * 256;
            int r = f >> 3;
            int c = (f & 7) << 2;
            float4 av = *reinterpret_cast<const float4*>(&A[(size_t)(m0 + r) * D_ + k0 + c]);
            As[c + 0][r] = av.x; As[c + 1][r] = av.y;
            As[c + 2][r] = av.z; As[c + 3][r] = av.w;
            float4 wv = *reinterpret_cast<const float4*>(&W[(size_t)(n0 + r) * D_ + k0 + c]);
            Bs[c + 0][r] = wv.x; Bs[c + 1][r] = wv.y;
            Bs[c + 2][r] = wv.z; Bs[c + 3][r] = wv.w;
        }
        __syncthreads();

        #pragma unroll 8
        for (int kk = 0; kk < BK; ++kk) {
            float4 a0 = *reinterpret_cast<const float4*>(&As[kk][ty * 8]);
            float4 a1 = *reinterpret_cast<const float4*>(&As[kk][ty * 8 + 4]);
            ulonglong2 bp0 = *reinterpret_cast<const ulonglong2*>(&Bs[kk][tx * 8]);
            ulonglong2 bp1 = *reinterpret_cast<const ulonglong2*>(&Bs[kk][tx * 8 + 4]);
            unsigned long long bv[4] = {bp0.x, bp0.y, bp1.x, bp1.y};
            float av[8] = {a0.x, a0.y, a0.z, a0.w, a1.x, a1.y, a1.z, a1.w};
            #pragma unroll
            for (int i = 0; i < 8; ++i) {
                unsigned long long aa = dup2(av[i]);
                #pragma unroll
                for (int j = 0; j < 4; ++j) ffma2(acc[i][j], aa, bv[j]);
            }
        }
        __syncthreads();
    }

    #pragma unroll
    for (int i = 0; i < 8; ++i) {
        int m = m0 + ty * 8 + i;
        int b  = m >> 11;
        int s  = m & (S_ - 1);
        #pragma unroll
        for (int j = 0; j < 4; ++j) {
            int n = n0 + tx * 8 + j * 2;
            float2 f = unpack2(acc[i][j]);
            int h  = n >> 6;
            int dk = n & (DK_ - 1);
            size_t base = (((size_t)b * H_ + h) * S_ + s) * DK_ + dk;
            Out[base]     = f.x + bias[n];
            Out[base + 1] = f.y + bias[n + 1];
        }
    }
}

// ---------------- tiled flash attention ----------------
// Q,K,V: [bh][s][dk] head-split. O: merged [b][s][h*DK+dk].
// 64 query rows x 64 keys per tile; 256 threads as 16x16, 4x4 per thread.
#define BR 64
#define BC 64

__global__ __launch_bounds__(256) void attn_kernel(
    const float* __restrict__ Q, const float* __restrict__ Kg,
    const float* __restrict__ V, float* __restrict__ O, int causal)
{
    __shared__ float Qs[DK_][BR + 4];   // transposed: [dk][row]
    __shared__ float Ks[DK_][BC + 4];   // transposed: [dk][key]
    __shared__ float Vs[BC][DK_];       // natural:    [key][dk]
    __shared__ float Ps[BC][BR + 4];    // transposed: [key][row]

    const int bh  = blockIdx.y;
    const int r0  = blockIdx.x * BR;
    const int tid = threadIdx.x;
    const int tx  = tid & 15;
    const int ty  = tid >> 4;

    // load Q tile transposed (once)
    {
        const float* qb = Q + ((size_t)bh * S_ + r0) * DK_;
        #pragma unroll
        for (int t = 0; t < 4; ++t) {
            int f = tid + t * 256;
            int r = f >> 4;
            int c = (f & 15) << 2;
            float4 a4 = *reinterpret_cast<const float4*>(&qb[r * DK_ + c]);
            Qs[c + 0][r] = a4.x; Qs[c + 1][r] = a4.y;
            Qs[c + 2][r] = a4.z; Qs[c + 3][r] = a4.w;
        }
    }

    float m[4], l[4];
    unsigned long long oacc[4][2];      // rows i=0..3, col-pairs jp=0..1
    #pragma unroll
    for (int i = 0; i < 4; ++i) {
        m[i] = -1e30f; l[i] = 0.f;
        oacc[i][0] = 0ull; oacc[i][1] = 0ull;
    }

    const int kend = causal ? (r0 + BR) : S_;
    for (int kt = 0; kt < kend; kt += BC) {
        __syncthreads();
        {
            const float* kb = Kg + ((size_t)bh * S_ + kt) * DK_;
            const float* vb = V  + ((size_t)bh * S_ + kt) * DK_;
            #pragma unroll
            for (int t = 0; t < 4; ++t) {
                int f = tid + t * 256;
                int r = f >> 4;
                int c = (f & 15) << 2;
                float4 a4 = *reinterpret_cast<const float4*>(&kb[r * DK_ + c]);
                Ks[c + 0][r] = a4.x; Ks[c + 1][r] = a4.y;
                Ks[c + 2][r] = a4.z; Ks[c + 3][r] = a4.w;
                *reinterpret_cast<float4*>(&Vs[r][c]) =
                    *reinterpret_cast<const float4*>(&vb[r * DK_ + c]);
            }
        }
        __syncthreads();

        // ---- S = Q @ K^T (64x64x64), packed f32x2 along keys ----
        unsigned long long s2[4][2];
        #pragma unroll
        for (int i = 0; i < 4; ++i) { s2[i][0] = 0ull; s2[i][1] = 0ull; }

        #pragma unroll 8
        for (int kk = 0; kk < DK_; ++kk) {
            float4 a = *reinterpret_cast<const float4*>(&Qs[kk][ty * 4]);
            ulonglong2 bp = *reinterpret_cast<const ulonglong2*>(&Ks[kk][tx * 4]);
            float av[4] = {a.x, a.y, a.z, a.w};
            #pragma unroll
            for (int i = 0; i < 4; ++i) {
                unsigned long long aa = dup2(av[i]);
                ffma2(s2[i][0], aa, bp.x);
                ffma2(s2[i][1], aa, bp.y);
            }
        }

        // unpack, scale, causal mask
        float s[4][4];
        const bool dmask = (causal && kt == r0);
        #pragma unroll
        for (int i = 0; i < 4; ++i) {
            float2 f0 = unpack2(s2[i][0]);
            float2 f1 = unpack2(s2[i][1]);
            s[i][0] = f0.x * 0.125f; s[i][1] = f0.y * 0.125f;
            s[i][2] = f1.x * 0.125f; s[i][3] = f1.y * 0.125f;
            if (dmask) {
                #pragma unroll
                for (int j = 0; j < 4; ++j)
                    if ((kt + tx * 4 + j) > (r0 + ty * 4 + i)) s[i][j] = -1e30f;
            }
        }

        // ---- online softmax per row ----
        #pragma unroll
        for (int i = 0; i < 4; ++i) {
            float mr = fmaxf(fmaxf(s[i][0], s[i][1]), fmaxf(s[i][2], s[i][3]));
            mr = fmaxf(mr, __shfl_xor_sync(0xffffffffu, mr, 1));
            mr = fmaxf(mr, __shfl_xor_sync(0xffffffffu, mr, 2));
            mr = fmaxf(mr, __shfl_xor_sync(0xffffffffu, mr, 4));
            mr = fmaxf(mr, __shfl_xor_sync(0xffffffffu, mr, 8));
            float nm   = fmaxf(m[i], mr);
            float corr = __expf(m[i] - nm);
            m[i] = nm;
            float rs = 0.f;
            #pragma unroll
            for (int j = 0; j < 4; ++j) {
                s[i][j] = __expf(s[i][j] - nm);
                rs += s[i][j];
            }
            rs += __shfl_xor_sync(0xffffffffu, rs, 1);
            rs += __shfl_xor_sync(0xffffffffu, rs, 2);
            rs += __shfl_xor_sync(0xffffffffu, rs, 4);
            rs += __shfl_xor_sync(0xffffffffu, rs, 8);
            l[i] = l[i] * corr + rs;
            unsigned long long cc = dup2(corr);
            fmul2(oacc[i][0], cc);
            fmul2(oacc[i][1], cc);
        }

        // store P transposed: Ps[key][row]
        #pragma unroll
        for (int j = 0; j < 4; ++j) {
            *reinterpret_cast<float4*>(&Ps[tx * 4 + j][ty * 4]) =
                make_float4(s[0][j], s[1][j], s[2][j], s[3][j]);
        }
        __syncthreads();

        // ---- O += P @ V (64x64x64), packed f32x2 along dk ----
        #pragma unroll 8
        for (int kk = 0; kk < BC; ++kk) {
            float4 a = *reinterpret_cast<const float4*>(&Ps[kk][ty * 4]);
            ulonglong2 bp = *reinterpret_cast<const ulonglong2*>(&Vs[kk][tx * 4]);
            float av[4] = {a.x, a.y, a.z, a.w};
            #pragma unroll
            for (int i = 0; i < 4; ++i) {
                unsigned long long aa = dup2(av[i]);
                ffma2(oacc[i][0], aa, bp.x);
                ffma2(oacc[i][1], aa, bp.y);
            }
        }
    }

    // epilogue: merged layout
    const int b = bh >> 3, h = bh & 7;
    #pragma unroll
    for (int i = 0; i < 4; ++i) {
        float inv = 1.f / l[i];
        float2 f0 = unpack2(oacc[i][0]);
        float2 f1 = unpack2(oacc[i][1]);
        float4 o4 = make_float4(f0.x * inv, f0.y * inv, f1.x * inv, f1.y * inv);
        *reinterpret_cast<float4*>(
            &O[((size_t)(b * S_ + r0 + ty * 4 + i)) * D_ + h * DK_ + tx * 4]) = o4;
    }
}

// ---------------- fused residual-add + LayerNorm ----------------
__global__ __launch_bounds__(256) void add_ln_kernel(
    const float* __restrict__ X, const float* __restrict__ Y,
    const float* __restrict__ gam, const float* __restrict__ bet,
    float* __restrict__ O)
{
    __shared__ float sh_s[8], sh_q[8];
    const int row = blockIdx.x;
    const int tid = threadIdx.x;
    const float* xp = X + (size_t)row * D_;
    const float* yp = Y + (size_t)row * D_;

    float v0 = xp[tid] + yp[tid];
    float v1 = xp[tid + 256] + yp[tid + 256];
    float s  = v0 + v1;
    float qq = v0 * v0 + v1 * v1;
    #pragma unroll
    for (int o = 16; o; o >>= 1) {
        s  += __shfl_xor_sync(0xffffffffu, s, o);
        qq += __shfl_xor_sync(0xffffffffu, qq, o);
    }
    if ((tid & 31) == 0) { sh_s[tid >> 5] = s; sh_q[tid >> 5] = qq; }
    __syncthreads();
    if (tid < 32) {
        float s2 = (tid < 8) ? sh_s[tid] : 0.f;
        float q2 = (tid < 8) ? sh_q[tid] : 0.f;
        #pragma unroll
        for (int o = 4; o; o >>= 1) {
            s2 += __shfl_xor_sync(0xffffffffu, s2, o);
            q2 += __shfl_xor_sync(0xffffffffu, q2, o);
        }
        if (tid == 0) { sh_s[0] = s2; sh_q[0] = q2; }
    }
    __syncthreads();

    const float mu  = sh_s[0] * (1.f / 512.f);
    const float var = sh_q[0] * (1.f / 512.f) - mu * mu;
    const float inv = rsqrtf(var + 1e-5f);
    O[(size_t)row * D_ + tid]       = (v0 - mu) * inv * gam[tid]       + bet[tid];
    O[(size_t)row * D_ + tid + 256] = (v1 - mu) * inv * gam[tid + 256] + bet[tid + 256];
}

// ---------------- orchestration ----------------
extern "C" void kernel_launch(void* const* d_in, const int* in_sizes, int n_in,
                              void* d_out, int out_size)
{
    const float* x_q   = (const float*)d_in[0];
    const float* x1    = (const float*)d_in[1];
    const float* x2    = (const float*)d_in[2];
    const float* sa_wq = (const float*)d_in[3];
    const float* sa_bq = (const float*)d_in[4];
    const float* sa_wk = (const float*)d_in[5];
    const float* sa_bk = (const float*)d_in[6];
    const float* sa_wv = (const float*)d_in[7];
    const float* sa_bv = (const float*)d_in[8];
    const float* ln1_g = (const float*)d_in[9];
    const float* ln1_b = (const float*)d_in[10];
    const float* in_w  = (const float*)d_in[11];
    const float* in_b  = (const float*)d_in[12];
    const float* out_w = (const float*)d_in[13];
    const float* out_b = (const float*)d_in[14];
    const float* ln2_g = (const float*)d_in[15];
    const float* ln2_b = (const float*)d_in[16];
    const float* w1    = (const float*)d_in[17];
    const float* b1    = (const float*)d_in[18];
    const float* w2    = (const float*)d_in[19];
    const float* b2    = (const float*)d_in[20];
    const float* ln3_g = (const float*)d_in[21];
    const float* ln3_b = (const float*)d_in[22];
    float* out = (float*)d_out;

    float *q, *k, *v, *ctx, *pr, *y, *ya, *ya2, *hb;
    cudaGetSymbolAddress((void**)&q,   g_q);
    cudaGetSymbolAddress((void**)&k,   g_k);
    cudaGetSymbolAddress((void**)&v,   g_v);
    cudaGetSymbolAddress((void**)&ctx, g_ctx);
    cudaGetSymbolAddress((void**)&pr,  g_pr);
    cudaGetSymbolAddress((void**)&y,   g_y);
    cudaGetSymbolAddress((void**)&ya,  g_ya);
    cudaGetSymbolAddress((void**)&ya2, g_ya2);
    cudaGetSymbolAddress((void**)&hb,  g_h);

    const dim3 blk(256);
    const dim3 gQKV(12, M_ / BM);        // (12, 32)
    const dim3 gD(D_ / BN, M_ / BM);     // (4, 32)
    const dim3 gF(FF_ / BN, M_ / BM);    // (16, 32)
    const dim3 gA(S_ / BR, B_ * H_);     // (32, 16)

    // ---- stage A: causal self-attention (no out-proj) ----
    qkv_kernel<<<gQKV, blk>>>(x_q, x_q, sa_wq, sa_wk, sa_wv,
                              sa_bq, sa_bk, sa_bv, q, k, v);
    attn_kernel<<<gA, blk>>>(q, k, v, ctx, 1);
    add_ln_kernel<<<M_, blk>>>(x_q, ctx, ln1_g, ln1_b, y);

    // ---- stage B: cross-attention with x1 ----
    qkv_kernel<<<gQKV, blk>>>(y, x1, in_w, in_w + D_*D_, in_w + 2*D_*D_,
                              in_b, in_b + D_, in_b + 2*D_, q, k, v);
    attn_kernel<<<gA, blk>>>(q, k, v, ctx, 0);
    gemm_kernel<<<gD, blk>>>(ctx, out_w, out_b, pr, M_, D_, D_, 0);
    add_ln_kernel<<<M_, blk>>>(y, pr, ln2_g, ln2_b, ya);

    // ---- stage C: cross-attention with x2 (same weights) ----
    qkv_kernel<<<gQKV, blk>>>(ya, x2, in_w, in_w + D_*D_, in_w + 2*D_*D_,
                              in_b, in_b + D_, in_b + 2*D_, q, k, v);
    attn_kernel<<<gA, blk>>>(q, k, v, ctx, 0);
    gemm_kernel<<<gD, blk>>>(ctx, out_w, out_b, pr, M_, D_, D_, 0);
    add_ln_kernel<<<M_, blk>>>(ya, pr, ln2_g, ln2_b, ya2);

    // ---- FFN ----
    gemm_kernel<<<gF, blk>>>(ya2, w1, b1, hb, M_, FF_, D_, 1);
    gemm_kernel<<<gD, blk>>>(hb,  w2, b2, pr, M_, D_, FF_, 0);
    add_ln_kernel<<<M_, blk>>>(ya2, pr, ln3_g, ln3_b, out);
}